// round 16
// baseline (speedup 1.0000x reference)
#include <cuda_runtime.h>
#include <cuda_bf16.h>
#include <cstdint>

#define BATCH 4
#define CCH   128
#define HH    128
#define WWID  128
#define NNODES (HH*WWID)
#define HEADS 8

typedef unsigned int u32;
typedef unsigned long long u64;

// ---------------- scratch (static device globals; no allocation) ----------------
__device__ float g_xp  [BATCH * NNODES * CCH];    // [B][N][C] projected features
__device__ float g_asrc[BATCH * NNODES * HEADS];
__device__ float g_adst[BATCH * NNODES * HEADS];
// Pre-baked W fragments for mma.sync m16n8k16 (A-operand = W^T, row-major [m=c_out][k=c_in])
__device__ u32 g_Wfrag[2 * 64 * 32 * 4];

// ---------------- packed f32x2 helpers ----------------
__device__ __forceinline__ u64 pack2_dup(float x) {
    u64 r; unsigned xi = __float_as_uint(x);
    asm("mov.b64 %0, {%1, %1};" : "=l"(r) : "r"(xi));
    return r;
}
__device__ __forceinline__ void fma2(u64& d, u64 a, u64 b) {
    asm("fma.rn.f32x2 %0, %1, %2, %0;" : "+l"(d) : "l"(a), "l"(b));
}
__device__ __forceinline__ float2 unpack2(u64 v) {
    unsigned lo, hi;
    asm("mov.b64 {%0, %1}, %2;" : "=r"(lo), "=r"(hi) : "l"(v));
    float2 f; f.x = __uint_as_float(lo); f.y = __uint_as_float(hi);
    return f;
}

// ---------------- mma.sync bf16 ----------------
__device__ __forceinline__ void mma_bf16(float* c, const u32* a, const u32* b) {
    asm volatile("mma.sync.aligned.m16n8k16.row.col.f32.bf16.bf16.f32 "
                 "{%0,%1,%2,%3}, {%4,%5,%6,%7}, {%8,%9}, {%0,%1,%2,%3};"
                 : "+f"(c[0]), "+f"(c[1]), "+f"(c[2]), "+f"(c[3])
                 : "r"(a[0]), "r"(a[1]), "r"(a[2]), "r"(a[3]),
                   "r"(b[0]), "r"(b[1]));
}

// ---------------- Kernel P: bake W^T hi/lo mma fragments ----------------
__global__ __launch_bounds__(256) void bprep_k(const float* __restrict__ Wl) {
    const int g = blockIdx.x * 256 + threadIdx.x;    // 0..8191
    const int r  = g & 3;
    const int l  = (g >> 2) & 31;
    const int mt = (g >> 7) & 7;
    const int kt = g >> 10;
    const int m = mt * 16 + (l >> 2) + (r & 1) * 8;
    const int k = kt * 16 + (l & 3) * 2 + (r >> 1) * 8;
    const float v0 = Wl[k * CCH + m];
    const float v1 = Wl[(k + 1) * CCH + m];
    u32 hp; asm("cvt.rn.bf16x2.f32 %0, %1, %2;" : "=r"(hp) : "f"(v1), "f"(v0));
    const float h0 = __uint_as_float(hp << 16);
    const float h1 = __uint_as_float(hp & 0xffff0000u);
    u32 lp; asm("cvt.rn.bf16x2.f32 %0, %1, %2;" : "=r"(lp) : "f"(v1 - h1), "f"(v0 - h0));
    g_Wfrag[g]        = hp;
    g_Wfrag[8192 + g] = lp;
}

// ---------------- Kernel A: bf16x3 HMMA GEMM (C^T form) + fused attention logits ----
#define XP_PITCH 136
#define SOFF_XH    0
#define SOFF_XL    34816
#define SOFF_OUT   0
#define OUT_PITCH  132
#define SMEM_MMA   (2 * 34816)

__global__ __launch_bounds__(256, 2) void mma_k(const float* __restrict__ x,
                                                const float* __restrict__ att_src,
                                                const float* __restrict__ att_dst,
                                                const int b) {
    extern __shared__ char smem[];
    u32*   s_xh = (u32*)(smem + SOFF_XH);        // [64 kp][XP_PITCH]
    u32*   s_xl = (u32*)(smem + SOFF_XL);
    float* s_o  = (float*)(smem + SOFF_OUT);     // [128 n][OUT_PITCH]

    const int tid  = threadIdx.x;
    const int wid  = tid >> 5;
    const int lane = tid & 31;
    const int m0   = blockIdx.x * 128;           // node base
    const float* xb = x + (size_t)b * CCH * NNODES + m0;

    // ---- load x tile, split hi/lo via cvt.bf16x2, pack k-pairs ----
    for (int t = tid; t < 64 * 128; t += 256) {
        const int kp = t >> 7;
        const int n  = t & 127;
        const float a0 = xb[(size_t)(2 * kp) * NNODES + n];
        const float a1 = xb[(size_t)(2 * kp + 1) * NNODES + n];
        u32 hp; asm("cvt.rn.bf16x2.f32 %0, %1, %2;" : "=r"(hp) : "f"(a1), "f"(a0));
        const float h0 = __uint_as_float(hp << 16);
        const float h1 = __uint_as_float(hp & 0xffff0000u);
        u32 lp; asm("cvt.rn.bf16x2.f32 %0, %1, %2;" : "=r"(lp) : "f"(a1 - h1), "f"(a0 - h0));
        s_xh[kp * XP_PITCH + n] = hp;
        s_xl[kp * XP_PITCH + n] = lp;
    }
    __syncthreads();

    // ---- mma mainloop: warp owns 16 nodes (2 n-groups of 8) x all 128 c_out ----
    const int n0 = wid * 16;
    float acc[8][2][4];
#pragma unroll
    for (int mt = 0; mt < 8; ++mt)
#pragma unroll
        for (int gg = 0; gg < 2; ++gg)
#pragma unroll
            for (int r = 0; r < 4; ++r) acc[mt][gg][r] = 0.f;

    const int nA  = n0 + (lane >> 2);
#pragma unroll
    for (int kt = 0; kt < 8; ++kt) {
        const int kp0 = kt * 8 + (lane & 3);
        u32 bh[2][2], bl[2][2];
#pragma unroll
        for (int gg = 0; gg < 2; ++gg) {
            const int nn = nA + gg * 8;
            bh[gg][0] = s_xh[kp0 * XP_PITCH + nn];
            bh[gg][1] = s_xh[(kp0 + 4) * XP_PITCH + nn];
            bl[gg][0] = s_xl[kp0 * XP_PITCH + nn];
            bl[gg][1] = s_xl[(kp0 + 4) * XP_PITCH + nn];
        }
#pragma unroll
        for (int mt = 0; mt < 8; ++mt) {
            const u32 fbase = ((u32)(kt * 8 + mt) * 32 + lane) * 4;
            u32 ah[4], al[4];
            *(uint4*)ah = __ldg((const uint4*)&g_Wfrag[fbase]);
            *(uint4*)al = __ldg((const uint4*)&g_Wfrag[8192 + fbase]);
#pragma unroll
            for (int gg = 0; gg < 2; ++gg) {
                mma_bf16(acc[mt][gg], ah, bh[gg]);   // hi*hi
                mma_bf16(acc[mt][gg], ah, bl[gg]);   // hi_w * lo_x
                mma_bf16(acc[mt][gg], al, bh[gg]);   // lo_w * hi_x
            }
        }
    }
    __syncthreads();   // all warps done reading Xp before s_o overwrites it

    // ---- scatter fragments to s_o[n][c] (warp-private rows; no sync needed after) ----
#pragma unroll
    for (int mt = 0; mt < 8; ++mt) {
        const int c = mt * 16 + (lane >> 2);
#pragma unroll
        for (int gg = 0; gg < 2; ++gg) {
            const int n = n0 + gg * 8 + (lane & 3) * 2;
            s_o[n * OUT_PITCH + c]           = acc[mt][gg][0];
            s_o[(n + 1) * OUT_PITCH + c]     = acc[mt][gg][1];
            s_o[n * OUT_PITCH + c + 8]       = acc[mt][gg][2];
            s_o[(n + 1) * OUT_PITCH + c + 8] = acc[mt][gg][3];
        }
    }

    // ---- epilogue: store xp [n][c] + fused attention logits (own rows only) ----
    const int cch = lane * 4;
    const float4 asv = *(const float4*)&att_src[cch];
    const float4 adv = *(const float4*)&att_dst[cch];
#pragma unroll 4
    for (int i = 0; i < 16; ++i) {
        const int nl = wid * 16 + i;
        const float4 v = *(const float4*)&s_o[nl * OUT_PITCH + cch];
        *(float4*)&g_xp[((size_t)b * NNODES + m0 + nl) * CCH + cch] = v;

        float s = v.x * asv.x + v.y * asv.y + v.z * asv.z + v.w * asv.w;
        float d = v.x * adv.x + v.y * adv.y + v.z * adv.z + v.w * adv.w;
        s += __shfl_xor_sync(0xffffffffu, s, 1);
        s += __shfl_xor_sync(0xffffffffu, s, 2);
        d += __shfl_xor_sync(0xffffffffu, d, 1);
        d += __shfl_xor_sync(0xffffffffu, d, 2);
        if ((lane & 3) == 0) {
            g_asrc[((size_t)b * NNODES + m0 + nl) * HEADS + (lane >> 2)] = s;
            g_adst[((size_t)b * NNODES + m0 + nl) * HEADS + (lane >> 2)] = d;
        }
    }
}

// ---------------- Kernel C: softmax-stencil aggregate + bias + ELU + LN + transpose store ----------------
#define TR 8
#define TC_T 8
#define HC 10
#define HNODES (10 * 10)
#define TNODES (TR * TC_T)
#define OPITCH 132
#define AGG_THREADS 512

#define SMEM_AGG ((HNODES * 128 + HNODES * 8 + TNODES * 8 + TNODES * OPITCH) * 4)

template <bool MASK>
__device__ __forceinline__ void agg_node(
    const int nl, const int lr, const int lc, const int rg, const int cg,
    const float* __restrict__ s_as, const float* __restrict__ s_ad,
    const float* __restrict__ s_xp, float* __restrict__ s_out,
    const int h, const int cch,
    const float4 bv, const float4 gv, const float4 be)
{
    const float adst = s_ad[nl * 8 + h];

    float e[9];
    float M = -1e30f;
#pragma unroll
    for (int m = 0; m < 9; ++m) {
        const int dr = m / 3 - 1, dc = m % 3 - 1;
        const int hrow = (lr + 1 + dr) * HC + (lc + 1 + dc);
        float sc = s_as[hrow * 8 + h] + adst;
        sc = sc > 0.f ? sc : 0.2f * sc;                 // leaky_relu(0.2)
        if (MASK) {
            const bool ok = ((unsigned)(rg + dr) < HH) && ((unsigned)(cg + dc) < WWID);
            sc = ok ? sc : -1e30f;
        }
        e[m] = sc;
        M = fmaxf(M, sc);
    }
    float den = 0.f;
#pragma unroll
    for (int m = 0; m < 9; ++m) { e[m] = __expf(e[m] - M); den += e[m]; }
    den += e[4];                                        // duplicated self-loop
    const float inv = __fdividef(1.0f, den);

    u64 acc01 = 0ull, acc23 = 0ull;
#pragma unroll
    for (int m = 0; m < 9; ++m) {
        float w = e[m] * inv;
        if (m == 4) w += w;                             // self counted twice
        const int dr = m / 3 - 1, dc = m % 3 - 1;
        const int hrow = (lr + 1 + dr) * HC + (lc + 1 + dc);
        const ulonglong2 v = *(const ulonglong2*)&s_xp[hrow * 128 + cch];
        const u64 wd = pack2_dup(w);
        fma2(acc01, wd, v.x);
        fma2(acc23, wd, v.y);
    }
    const float2 p01 = unpack2(acc01);
    const float2 p23 = unpack2(acc23);

    float o0 = p01.x + bv.x, o1 = p01.y + bv.y, o2 = p23.x + bv.z, o3 = p23.y + bv.w;
    o0 = o0 > 0.f ? o0 : (__expf(o0) - 1.f);
    o1 = o1 > 0.f ? o1 : (__expf(o1) - 1.f);
    o2 = o2 > 0.f ? o2 : (__expf(o2) - 1.f);
    o3 = o3 > 0.f ? o3 : (__expf(o3) - 1.f);
    float sum = o0 + o1 + o2 + o3;
    float sq  = o0 * o0 + o1 * o1 + o2 * o2 + o3 * o3;
#pragma unroll
    for (int off = 16; off; off >>= 1) {
        sum += __shfl_xor_sync(0xffffffffu, sum, off);
        sq  += __shfl_xor_sync(0xffffffffu, sq,  off);
    }
    const float mu   = sum * 0.0078125f;
    const float var  = sq * 0.0078125f - mu * mu;
    const float rstd = rsqrtf(var + 1e-5f);

    float4 y;
    y.x = (o0 - mu) * rstd * gv.x + be.x;
    y.y = (o1 - mu) * rstd * gv.y + be.y;
    y.z = (o2 - mu) * rstd * gv.z + be.z;
    y.w = (o3 - mu) * rstd * gv.w + be.w;
    *(float4*)&s_out[nl * OPITCH + cch] = y;
}

__global__ __launch_bounds__(AGG_THREADS, 2) void agg_k(const float* __restrict__ bias,
                                                        const float* __restrict__ gamma,
                                                        const float* __restrict__ beta,
                                                        float* __restrict__ out,
                                                        const int b) {
    extern __shared__ float sm[];
    float* s_xp  = sm;                          // [HNODES][128]
    float* s_as  = s_xp + HNODES * 128;         // [HNODES][8]
    float* s_ad  = s_as + HNODES * 8;           // [TNODES][8]
    float* s_out = s_ad + TNODES * 8;           // [TNODES][OPITCH]

    const int r0 = blockIdx.y * TR;
    const int c0 = blockIdx.x * TC_T;
    const float* xpb = g_xp   + (size_t)b * NNODES * CCH;
    const float* asb = g_asrc + (size_t)b * NNODES * HEADS;
    const float* adb = g_adst + (size_t)b * NNODES * HEADS;

    for (int t = threadIdx.x; t < HNODES * 32; t += AGG_THREADS) {
        const int row = t >> 5;
        const int pos = (t & 31) << 2;
        const int hr = row / HC, hc = row - hr * HC;
        const int rg = r0 - 1 + hr, cg = c0 - 1 + hc;
        float4 v = {0.f, 0.f, 0.f, 0.f};
        if ((unsigned)rg < HH && (unsigned)cg < WWID)
            v = *(const float4*)&xpb[(size_t)(rg * WWID + cg) * CCH + pos];
        *(float4*)&s_xp[row * 128 + pos] = v;
    }
    for (int t = threadIdx.x; t < HNODES * 8; t += AGG_THREADS) {
        const int row = t >> 3;
        const int hr = row / HC, hc = row - hr * HC;
        const int rg = r0 - 1 + hr, cg = c0 - 1 + hc;
        float v = 0.f;
        if ((unsigned)rg < HH && (unsigned)cg < WWID)
            v = asb[(rg * WWID + cg) * HEADS + (t & 7)];
        s_as[t] = v;
    }
    for (int t = threadIdx.x; t < TNODES * 8; t += AGG_THREADS) {
        const int node = t >> 3;
        const int lr = node >> 3, lc = node & 7;
        s_ad[t] = adb[((r0 + lr) * WWID + c0 + lc) * HEADS + (t & 7)];
    }
    __syncthreads();

    const int warp = threadIdx.x >> 5;
    const int lane = threadIdx.x & 31;
    const int h    = lane >> 2;
    const int cch  = lane << 2;

    const float4 bv = *(const float4*)&bias[cch];
    const float4 gv = *(const float4*)&gamma[cch];
    const float4 be = *(const float4*)&beta[cch];

    const bool interior = (r0 > 0) && (r0 < HH - TR) && (c0 > 0) && (c0 < WWID - TC_T);
    if (interior) {
#pragma unroll 1
        for (int i = 0; i < 4; ++i) {
            const int nl = warp * 4 + i;
            const int lr = nl >> 3, lc = nl & 7;
            agg_node<false>(nl, lr, lc, r0 + lr, c0 + lc,
                            s_as, s_ad, s_xp, s_out, h, cch, bv, gv, be);
        }
    } else {
#pragma unroll 1
        for (int i = 0; i < 4; ++i) {
            const int nl = warp * 4 + i;
            const int lr = nl >> 3, lc = nl & 7;
            agg_node<true>(nl, lr, lc, r0 + lr, c0 + lc,
                           s_as, s_ad, s_xp, s_out, h, cch, bv, gv, be);
        }
    }
    __syncthreads();

    // ---- transposed store: float4 LDS (conflict-free) + 4 plane-strided STGs ----
    float* ob = out + (size_t)b * CCH * NNODES + (size_t)r0 * WWID + c0;
#pragma unroll
    for (int g = 0; g < 4; ++g) {
        const int t = threadIdx.x + AGG_THREADS * g;   // 0..2047
        const int node = t & 63;
        const int cg   = t >> 6;                       // channel group 0..31
        const float4 v = *(const float4*)&s_out[node * OPITCH + cg * 4];
        const int lr = node >> 3, lc = node & 7;
        float* p = ob + (size_t)(cg * 4) * NNODES + lr * WWID + lc;
        p[0]          = v.x;
        p[NNODES]     = v.y;
        p[2 * NNODES] = v.z;
        p[3 * NNODES] = v.w;
    }
}

// ---------------- launch: 2-stream software pipeline (capture-legal fork/join) ----------------
extern "C" void kernel_launch(void* const* d_in, const int* in_sizes, int n_in,
                              void* d_out, int out_size) {
    const float* x       = (const float*)d_in[0];
    const float* Wl      = (const float*)d_in[1];
    const float* att_src = (const float*)d_in[2];
    const float* att_dst = (const float*)d_in[3];
    const float* bias    = (const float*)d_in[4];
    const float* gamma   = (const float*)d_in[5];
    const float* beta    = (const float*)d_in[6];
    float* out = (float*)d_out;

    static cudaStream_t sA = nullptr, sB = nullptr;
    static cudaEvent_t evRoot = nullptr, evM[BATCH], evDone = nullptr;
    if (sA == nullptr) {
        cudaStreamCreateWithFlags(&sA, cudaStreamNonBlocking);
        cudaStreamCreateWithFlags(&sB, cudaStreamNonBlocking);
        cudaEventCreateWithFlags(&evRoot, cudaEventDisableTiming);
        for (int i = 0; i < BATCH; ++i) cudaEventCreateWithFlags(&evM[i], cudaEventDisableTiming);
        cudaEventCreateWithFlags(&evDone, cudaEventDisableTiming);
        cudaFuncSetAttribute(mma_k, cudaFuncAttributeMaxDynamicSharedMemorySize, SMEM_MMA);
        cudaFuncSetAttribute(agg_k, cudaFuncAttributeMaxDynamicSharedMemorySize, SMEM_AGG);
    }

    // fork both side streams off the capturing (default) stream
    cudaEventRecord(evRoot, 0);
    cudaStreamWaitEvent(sA, evRoot, 0);
    cudaStreamWaitEvent(sB, evRoot, 0);

    bprep_k<<<32, 256, 0, sA>>>(Wl);
    for (int b = 0; b < BATCH; ++b) {
        mma_k<<<NNODES / 128, 256, SMEM_MMA, sA>>>(x, att_src, att_dst, b);
        cudaEventRecord(evM[b], sA);
        cudaStreamWaitEvent(sB, evM[b], 0);
        agg_k<<<dim3(WWID / TC_T, HH / TR), AGG_THREADS, SMEM_AGG, sB>>>(bias, gamma, beta, out, b);
    }

    // join back into the capturing stream
    cudaEventRecord(evDone, sB);
    cudaStreamWaitEvent(0, evDone, 0);
}

// round 17
// speedup vs baseline: 1.1758x; 1.1758x over previous
#include <cuda_runtime.h>
#include <cuda_bf16.h>
#include <cstdint>

#define BATCH 4
#define CCH   128
#define HH    128
#define WWID  128
#define NNODES (HH*WWID)
#define HEADS 8

typedef unsigned int u32;
typedef unsigned long long u64;

// ---------------- scratch (static device globals; no allocation) ----------------
__device__ float g_xp  [BATCH * NNODES * CCH];    // [B][N][C] projected features
__device__ float g_asrc[BATCH * NNODES * HEADS];
__device__ float g_adst[BATCH * NNODES * HEADS];
// Pre-baked W fragments for mma.sync m16n8k16 (A-operand = W^T, row-major [m=c_out][k=c_in])
__device__ u32 g_Wfrag[2 * 64 * 32 * 4];

// ---------------- packed f32x2 helpers ----------------
__device__ __forceinline__ u64 pack2_dup(float x) {
    u64 r; unsigned xi = __float_as_uint(x);
    asm("mov.b64 %0, {%1, %1};" : "=l"(r) : "r"(xi));
    return r;
}
__device__ __forceinline__ void fma2(u64& d, u64 a, u64 b) {
    asm("fma.rn.f32x2 %0, %1, %2, %0;" : "+l"(d) : "l"(a), "l"(b));
}
__device__ __forceinline__ float2 unpack2(u64 v) {
    unsigned lo, hi;
    asm("mov.b64 {%0, %1}, %2;" : "=r"(lo), "=r"(hi) : "l"(v));
    float2 f; f.x = __uint_as_float(lo); f.y = __uint_as_float(hi);
    return f;
}

// ---------------- mma.sync bf16 ----------------
__device__ __forceinline__ void mma_bf16(float* c, const u32* a, const u32* b) {
    asm volatile("mma.sync.aligned.m16n8k16.row.col.f32.bf16.bf16.f32 "
                 "{%0,%1,%2,%3}, {%4,%5,%6,%7}, {%8,%9}, {%0,%1,%2,%3};"
                 : "+f"(c[0]), "+f"(c[1]), "+f"(c[2]), "+f"(c[3])
                 : "r"(a[0]), "r"(a[1]), "r"(a[2]), "r"(a[3]),
                   "r"(b[0]), "r"(b[1]));
}

// ---------------- Kernel P: bake W^T hi/lo mma fragments ----------------
__global__ __launch_bounds__(256) void bprep_k(const float* __restrict__ Wl) {
    const int g = blockIdx.x * 256 + threadIdx.x;    // 0..8191
    const int r  = g & 3;
    const int l  = (g >> 2) & 31;
    const int mt = (g >> 7) & 7;
    const int kt = g >> 10;
    const int m = mt * 16 + (l >> 2) + (r & 1) * 8;
    const int k = kt * 16 + (l & 3) * 2 + (r >> 1) * 8;
    const float v0 = Wl[k * CCH + m];
    const float v1 = Wl[(k + 1) * CCH + m];
    u32 hp; asm("cvt.rn.bf16x2.f32 %0, %1, %2;" : "=r"(hp) : "f"(v1), "f"(v0));
    const float h0 = __uint_as_float(hp << 16);
    const float h1 = __uint_as_float(hp & 0xffff0000u);
    u32 lp; asm("cvt.rn.bf16x2.f32 %0, %1, %2;" : "=r"(lp) : "f"(v1 - h1), "f"(v0 - h0));
    g_Wfrag[g]        = hp;
    g_Wfrag[8192 + g] = lp;
}

// ---------------- Kernel A: bf16x3 HMMA GEMM (C^T form) + fused attention logits ----
#define XP_PITCH 136
#define SOFF_XH    0
#define SOFF_XL    34816
#define SOFF_OUT   0
#define OUT_PITCH  132
#define SMEM_MMA   (2 * 34816)

__global__ __launch_bounds__(256, 2) void mma_k(const float* __restrict__ x,
                                                const float* __restrict__ att_src,
                                                const float* __restrict__ att_dst,
                                                const int b0) {
    extern __shared__ char smem[];
    u32*   s_xh = (u32*)(smem + SOFF_XH);        // [64 kp][XP_PITCH]
    u32*   s_xl = (u32*)(smem + SOFF_XL);
    float* s_o  = (float*)(smem + SOFF_OUT);     // [128 n][OUT_PITCH]

    const int tid  = threadIdx.x;
    const int wid  = tid >> 5;
    const int lane = tid & 31;
    const int b    = b0 + blockIdx.y;            // batch = pair base + y
    const int m0   = blockIdx.x * 128;           // node base
    const float* xb = x + (size_t)b * CCH * NNODES + m0;

    // ---- load x tile, split hi/lo via cvt.bf16x2, pack k-pairs ----
    for (int t = tid; t < 64 * 128; t += 256) {
        const int kp = t >> 7;
        const int n  = t & 127;
        const float a0 = xb[(size_t)(2 * kp) * NNODES + n];
        const float a1 = xb[(size_t)(2 * kp + 1) * NNODES + n];
        u32 hp; asm("cvt.rn.bf16x2.f32 %0, %1, %2;" : "=r"(hp) : "f"(a1), "f"(a0));
        const float h0 = __uint_as_float(hp << 16);
        const float h1 = __uint_as_float(hp & 0xffff0000u);
        u32 lp; asm("cvt.rn.bf16x2.f32 %0, %1, %2;" : "=r"(lp) : "f"(a1 - h1), "f"(a0 - h0));
        s_xh[kp * XP_PITCH + n] = hp;
        s_xl[kp * XP_PITCH + n] = lp;
    }
    __syncthreads();

    // ---- mma mainloop: warp owns 16 nodes (2 n-groups of 8) x all 128 c_out ----
    const int n0 = wid * 16;
    float acc[8][2][4];
#pragma unroll
    for (int mt = 0; mt < 8; ++mt)
#pragma unroll
        for (int gg = 0; gg < 2; ++gg)
#pragma unroll
            for (int r = 0; r < 4; ++r) acc[mt][gg][r] = 0.f;

    const int nA  = n0 + (lane >> 2);
#pragma unroll
    for (int kt = 0; kt < 8; ++kt) {
        const int kp0 = kt * 8 + (lane & 3);
        u32 bh[2][2], bl[2][2];
#pragma unroll
        for (int gg = 0; gg < 2; ++gg) {
            const int nn = nA + gg * 8;
            bh[gg][0] = s_xh[kp0 * XP_PITCH + nn];
            bh[gg][1] = s_xh[(kp0 + 4) * XP_PITCH + nn];
            bl[gg][0] = s_xl[kp0 * XP_PITCH + nn];
            bl[gg][1] = s_xl[(kp0 + 4) * XP_PITCH + nn];
        }
#pragma unroll
        for (int mt = 0; mt < 8; ++mt) {
            const u32 fbase = ((u32)(kt * 8 + mt) * 32 + lane) * 4;
            u32 ah[4], al[4];
            *(uint4*)ah = __ldg((const uint4*)&g_Wfrag[fbase]);
            *(uint4*)al = __ldg((const uint4*)&g_Wfrag[8192 + fbase]);
#pragma unroll
            for (int gg = 0; gg < 2; ++gg) {
                mma_bf16(acc[mt][gg], ah, bh[gg]);   // hi*hi
                mma_bf16(acc[mt][gg], ah, bl[gg]);   // hi_w * lo_x
                mma_bf16(acc[mt][gg], al, bh[gg]);   // lo_w * hi_x
            }
        }
    }
    __syncthreads();   // all warps done reading Xp before s_o overwrites it

    // ---- scatter fragments to s_o[n][c] (warp-private rows; no sync needed after) ----
#pragma unroll
    for (int mt = 0; mt < 8; ++mt) {
        const int c = mt * 16 + (lane >> 2);
#pragma unroll
        for (int gg = 0; gg < 2; ++gg) {
            const int n = n0 + gg * 8 + (lane & 3) * 2;
            s_o[n * OUT_PITCH + c]           = acc[mt][gg][0];
            s_o[(n + 1) * OUT_PITCH + c]     = acc[mt][gg][1];
            s_o[n * OUT_PITCH + c + 8]       = acc[mt][gg][2];
            s_o[(n + 1) * OUT_PITCH + c + 8] = acc[mt][gg][3];
        }
    }

    // ---- epilogue: store xp [n][c] + fused attention logits (own rows only) ----
    const int cch = lane * 4;
    const float4 asv = *(const float4*)&att_src[cch];
    const float4 adv = *(const float4*)&att_dst[cch];
#pragma unroll 4
    for (int i = 0; i < 16; ++i) {
        const int nl = wid * 16 + i;
        const float4 v = *(const float4*)&s_o[nl * OUT_PITCH + cch];
        *(float4*)&g_xp[((size_t)b * NNODES + m0 + nl) * CCH + cch] = v;

        float s = v.x * asv.x + v.y * asv.y + v.z * asv.z + v.w * asv.w;
        float d = v.x * adv.x + v.y * adv.y + v.z * adv.z + v.w * adv.w;
        s += __shfl_xor_sync(0xffffffffu, s, 1);
        s += __shfl_xor_sync(0xffffffffu, s, 2);
        d += __shfl_xor_sync(0xffffffffu, d, 1);
        d += __shfl_xor_sync(0xffffffffu, d, 2);
        if ((lane & 3) == 0) {
            g_asrc[((size_t)b * NNODES + m0 + nl) * HEADS + (lane >> 2)] = s;
            g_adst[((size_t)b * NNODES + m0 + nl) * HEADS + (lane >> 2)] = d;
        }
    }
}

// ---------------- Kernel C: softmax-stencil aggregate + bias + ELU + LN + transpose store ----------------
#define TR 8
#define TC_T 8
#define HC 10
#define HNODES (10 * 10)
#define TNODES (TR * TC_T)
#define OPITCH 132
#define AGG_THREADS 512

#define SMEM_AGG ((HNODES * 128 + HNODES * 8 + TNODES * 8 + TNODES * OPITCH) * 4)

template <bool MASK>
__device__ __forceinline__ void agg_node(
    const int nl, const int lr, const int lc, const int rg, const int cg,
    const float* __restrict__ s_as, const float* __restrict__ s_ad,
    const float* __restrict__ s_xp, float* __restrict__ s_out,
    const int h, const int cch,
    const float4 bv, const float4 gv, const float4 be)
{
    const float adst = s_ad[nl * 8 + h];

    float e[9];
    float M = -1e30f;
#pragma unroll
    for (int m = 0; m < 9; ++m) {
        const int dr = m / 3 - 1, dc = m % 3 - 1;
        const int hrow = (lr + 1 + dr) * HC + (lc + 1 + dc);
        float sc = s_as[hrow * 8 + h] + adst;
        sc = sc > 0.f ? sc : 0.2f * sc;                 // leaky_relu(0.2)
        if (MASK) {
            const bool ok = ((unsigned)(rg + dr) < HH) && ((unsigned)(cg + dc) < WWID);
            sc = ok ? sc : -1e30f;
        }
        e[m] = sc;
        M = fmaxf(M, sc);
    }
    float den = 0.f;
#pragma unroll
    for (int m = 0; m < 9; ++m) { e[m] = __expf(e[m] - M); den += e[m]; }
    den += e[4];                                        // duplicated self-loop
    const float inv = __fdividef(1.0f, den);

    u64 acc01 = 0ull, acc23 = 0ull;
#pragma unroll
    for (int m = 0; m < 9; ++m) {
        float w = e[m] * inv;
        if (m == 4) w += w;                             // self counted twice
        const int dr = m / 3 - 1, dc = m % 3 - 1;
        const int hrow = (lr + 1 + dr) * HC + (lc + 1 + dc);
        const ulonglong2 v = *(const ulonglong2*)&s_xp[hrow * 128 + cch];
        const u64 wd = pack2_dup(w);
        fma2(acc01, wd, v.x);
        fma2(acc23, wd, v.y);
    }
    const float2 p01 = unpack2(acc01);
    const float2 p23 = unpack2(acc23);

    float o0 = p01.x + bv.x, o1 = p01.y + bv.y, o2 = p23.x + bv.z, o3 = p23.y + bv.w;
    o0 = o0 > 0.f ? o0 : (__expf(o0) - 1.f);
    o1 = o1 > 0.f ? o1 : (__expf(o1) - 1.f);
    o2 = o2 > 0.f ? o2 : (__expf(o2) - 1.f);
    o3 = o3 > 0.f ? o3 : (__expf(o3) - 1.f);
    float sum = o0 + o1 + o2 + o3;
    float sq  = o0 * o0 + o1 * o1 + o2 * o2 + o3 * o3;
#pragma unroll
    for (int off = 16; off; off >>= 1) {
        sum += __shfl_xor_sync(0xffffffffu, sum, off);
        sq  += __shfl_xor_sync(0xffffffffu, sq,  off);
    }
    const float mu   = sum * 0.0078125f;
    const float var  = sq * 0.0078125f - mu * mu;
    const float rstd = rsqrtf(var + 1e-5f);

    float4 y;
    y.x = (o0 - mu) * rstd * gv.x + be.x;
    y.y = (o1 - mu) * rstd * gv.y + be.y;
    y.z = (o2 - mu) * rstd * gv.z + be.z;
    y.w = (o3 - mu) * rstd * gv.w + be.w;
    *(float4*)&s_out[nl * OPITCH + cch] = y;
}

__global__ __launch_bounds__(AGG_THREADS, 2) void agg_k(const float* __restrict__ bias,
                                                        const float* __restrict__ gamma,
                                                        const float* __restrict__ beta,
                                                        float* __restrict__ out,
                                                        const int b0) {
    extern __shared__ float sm[];
    float* s_xp  = sm;                          // [HNODES][128]
    float* s_as  = s_xp + HNODES * 128;         // [HNODES][8]
    float* s_ad  = s_as + HNODES * 8;           // [TNODES][8]
    float* s_out = s_ad + TNODES * 8;           // [TNODES][OPITCH]

    const int b  = b0 + blockIdx.z;             // batch = pair base + z
    const int r0 = blockIdx.y * TR;
    const int c0 = blockIdx.x * TC_T;
    const float* xpb = g_xp   + (size_t)b * NNODES * CCH;
    const float* asb = g_asrc + (size_t)b * NNODES * HEADS;
    const float* adb = g_adst + (size_t)b * NNODES * HEADS;

    for (int t = threadIdx.x; t < HNODES * 32; t += AGG_THREADS) {
        const int row = t >> 5;
        const int pos = (t & 31) << 2;
        const int hr = row / HC, hc = row - hr * HC;
        const int rg = r0 - 1 + hr, cg = c0 - 1 + hc;
        float4 v = {0.f, 0.f, 0.f, 0.f};
        if ((unsigned)rg < HH && (unsigned)cg < WWID)
            v = *(const float4*)&xpb[(size_t)(rg * WWID + cg) * CCH + pos];
        *(float4*)&s_xp[row * 128 + pos] = v;
    }
    for (int t = threadIdx.x; t < HNODES * 8; t += AGG_THREADS) {
        const int row = t >> 3;
        const int hr = row / HC, hc = row - hr * HC;
        const int rg = r0 - 1 + hr, cg = c0 - 1 + hc;
        float v = 0.f;
        if ((unsigned)rg < HH && (unsigned)cg < WWID)
            v = asb[(rg * WWID + cg) * HEADS + (t & 7)];
        s_as[t] = v;
    }
    for (int t = threadIdx.x; t < TNODES * 8; t += AGG_THREADS) {
        const int node = t >> 3;
        const int lr = node >> 3, lc = node & 7;
        s_ad[t] = adb[((r0 + lr) * WWID + c0 + lc) * HEADS + (t & 7)];
    }
    __syncthreads();

    const int warp = threadIdx.x >> 5;
    const int lane = threadIdx.x & 31;
    const int h    = lane >> 2;
    const int cch  = lane << 2;

    const float4 bv = *(const float4*)&bias[cch];
    const float4 gv = *(const float4*)&gamma[cch];
    const float4 be = *(const float4*)&beta[cch];

    const bool interior = (r0 > 0) && (r0 < HH - TR) && (c0 > 0) && (c0 < WWID - TC_T);
    if (interior) {
#pragma unroll 1
        for (int i = 0; i < 4; ++i) {
            const int nl = warp * 4 + i;
            const int lr = nl >> 3, lc = nl & 7;
            agg_node<false>(nl, lr, lc, r0 + lr, c0 + lc,
                            s_as, s_ad, s_xp, s_out, h, cch, bv, gv, be);
        }
    } else {
#pragma unroll 1
        for (int i = 0; i < 4; ++i) {
            const int nl = warp * 4 + i;
            const int lr = nl >> 3, lc = nl & 7;
            agg_node<true>(nl, lr, lc, r0 + lr, c0 + lc,
                           s_as, s_ad, s_xp, s_out, h, cch, bv, gv, be);
        }
    }
    __syncthreads();

    // ---- transposed store: float4 LDS (conflict-free) + 4 plane-strided STGs ----
    float* ob = out + (size_t)b * CCH * NNODES + (size_t)r0 * WWID + c0;
#pragma unroll
    for (int g = 0; g < 4; ++g) {
        const int t = threadIdx.x + AGG_THREADS * g;   // 0..2047
        const int node = t & 63;
        const int cg   = t >> 6;                       // channel group 0..31
        const float4 v = *(const float4*)&s_out[node * OPITCH + cg * 4];
        const int lr = node >> 3, lc = node & 7;
        float* p = ob + (size_t)(cg * 4) * NNODES + lr * WWID + lc;
        p[0]          = v.x;
        p[NNODES]     = v.y;
        p[2 * NNODES] = v.z;
        p[3 * NNODES] = v.w;
    }
}

// ---------------- launch: 2-stream pipeline over batch PAIRS (capture-legal fork/join) ----------------
extern "C" void kernel_launch(void* const* d_in, const int* in_sizes, int n_in,
                              void* d_out, int out_size) {
    const float* x       = (const float*)d_in[0];
    const float* Wl      = (const float*)d_in[1];
    const float* att_src = (const float*)d_in[2];
    const float* att_dst = (const float*)d_in[3];
    const float* bias    = (const float*)d_in[4];
    const float* gamma   = (const float*)d_in[5];
    const float* beta    = (const float*)d_in[6];
    float* out = (float*)d_out;

    static cudaStream_t sA = nullptr, sB = nullptr;
    static cudaEvent_t evRoot = nullptr, evM0 = nullptr, evM1 = nullptr, evDone = nullptr;
    if (sA == nullptr) {
        cudaStreamCreateWithFlags(&sA, cudaStreamNonBlocking);
        cudaStreamCreateWithFlags(&sB, cudaStreamNonBlocking);
        cudaEventCreateWithFlags(&evRoot, cudaEventDisableTiming);
        cudaEventCreateWithFlags(&evM0, cudaEventDisableTiming);
        cudaEventCreateWithFlags(&evM1, cudaEventDisableTiming);
        cudaEventCreateWithFlags(&evDone, cudaEventDisableTiming);
        cudaFuncSetAttribute(mma_k, cudaFuncAttributeMaxDynamicSharedMemorySize, SMEM_MMA);
        cudaFuncSetAttribute(agg_k, cudaFuncAttributeMaxDynamicSharedMemorySize, SMEM_AGG);
    }

    // fork both side streams off the capturing (default) stream
    cudaEventRecord(evRoot, 0);
    cudaStreamWaitEvent(sA, evRoot, 0);
    cudaStreamWaitEvent(sB, evRoot, 0);

    bprep_k<<<32, 256, 0, sA>>>(Wl);

    // pair {0,1}: mma on A, then agg on B while A runs pair {2,3}
    mma_k<<<dim3(NNODES / 128, 2), 256, SMEM_MMA, sA>>>(x, att_src, att_dst, 0);
    cudaEventRecord(evM0, sA);

    mma_k<<<dim3(NNODES / 128, 2), 256, SMEM_MMA, sA>>>(x, att_src, att_dst, 2);
    cudaEventRecord(evM1, sA);

    cudaStreamWaitEvent(sB, evM0, 0);
    agg_k<<<dim3(WWID / TC_T, HH / TR, 2), AGG_THREADS, SMEM_AGG, sB>>>(bias, gamma, beta, out, 0);

    cudaStreamWaitEvent(sB, evM1, 0);
    agg_k<<<dim3(WWID / TC_T, HH / TR, 2), AGG_THREADS, SMEM_AGG, sB>>>(bias, gamma, beta, out, 2);

    // join back into the capturing stream
    cudaEventRecord(evDone, sB);
    cudaStreamWaitEvent(0, evDone, 0);
}